// round 14
// baseline (speedup 1.0000x reference)
// R13: per-launch dynamic smem (M64 batches -> 7 blocks/SM), wo/down split bump, merged odd attention.
#include <cuda_runtime.h>
#include <cuda_fp16.h>
#include <math.h>
#include <stdint.h>

#define L_LAYERS 16
#define HD 64
#define NH 15
#define NKV 5
#define TH 960
#define TI 2560
#define EH 720
#define EI 2048
#define PL 512
#define EL 128
#define SS 640
#define QW (NH*HD)   // 960
#define KW (NKV*HD)  // 320

// ---------------- weight half cache ----------------
#define N_VQ  ((size_t)L_LAYERS*TH*QW)
#define N_VK  ((size_t)L_LAYERS*TH*KW)
#define N_VV  ((size_t)L_LAYERS*TH*KW)
#define N_VO  ((size_t)L_LAYERS*QW*TH)
#define N_VG  ((size_t)L_LAYERS*TH*TI)
#define N_VU  ((size_t)L_LAYERS*TH*TI)
#define N_VD  ((size_t)L_LAYERS*TI*TH)
#define N_EQ  ((size_t)L_LAYERS*EH*QW)
#define N_EKS ((size_t)(L_LAYERS/2)*EH*KW)
#define N_EVS ((size_t)(L_LAYERS/2)*EH*KW)
#define N_EKC ((size_t)(L_LAYERS/2)*KW*KW)
#define N_EVC ((size_t)(L_LAYERS/2)*KW*KW)
#define N_EO  ((size_t)L_LAYERS*QW*EH)
#define N_EG  ((size_t)L_LAYERS*EH*EI)
#define N_EU  ((size_t)L_LAYERS*EH*EI)
#define N_ED  ((size_t)L_LAYERS*EI*EH)

#define O_VQ  ((size_t)0)
#define O_VK  (O_VQ + N_VQ)
#define O_VV  (O_VK + N_VK)
#define O_VO  (O_VV + N_VV)
#define O_VG  (O_VO + N_VO)
#define O_VU  (O_VG + N_VG)
#define O_VD  (O_VU + N_VU)
#define O_EQ  (O_VD + N_VD)
#define O_EKS (O_EQ + N_EQ)
#define O_EVS (O_EKS + N_EKS)
#define O_EKC (O_EVS + N_EVS)
#define O_EVC (O_EKC + N_EKC)
#define O_EO  (O_EVC + N_EVC)
#define O_EG  (O_EO + N_EO)
#define O_EU  (O_EG + N_EG)
#define O_ED  (O_EU + N_EU)
#define W_TOTAL (O_ED + N_ED)

__device__ __align__(128) __half g_wh[W_TOTAL];

// ---------------- activation / residual scratch ----------------
__device__ __align__(128) float  g_vlm[PL*TH];
__device__ __align__(128) float  g_exp[EL*EH];
__device__ __align__(128) float  g_m1 [PL*TI];
__device__ __align__(128) float  g_m2 [PL*TI];
__device__ __align__(128) float  g_e1 [EL*EI];
__device__ __align__(128) float  g_e2 [EL*EI];
__device__ __align__(128) __half h_hv [PL*TH];
__device__ __align__(128) __half h_he [EL*EH];
__device__ __align__(128) __half h_q  [SS*QW];
__device__ __align__(128) __half h_k  [SS*KW];
__device__ __align__(128) __half h_v  [SS*KW];
__device__ __align__(128) __half h_ke [PL*KW];
__device__ __align__(128) __half h_ve [PL*KW];
__device__ __align__(128) __half h_att[SS*QW];
__device__ __align__(128) __half h_m2 [PL*TI];
__device__ __align__(128) __half h_e2 [EL*EI];

// ---------------- PTX helpers ----------------
__device__ __forceinline__ uint32_t smem_u32(const void* p) {
    uint32_t a;
    asm("{ .reg .u64 t; cvta.to.shared.u64 t, %1; cvt.u32.u64 %0, t; }" : "=r"(a) : "l"(p));
    return a;
}
__device__ __forceinline__ void cpasync16(uint32_t s, const void* g, int sz) {
    asm volatile("cp.async.ca.shared.global [%0], [%1], 16, %2;" :: "r"(s), "l"(g), "r"(sz));
}
__device__ __forceinline__ void cp_commit() { asm volatile("cp.async.commit_group;"); }
__device__ __forceinline__ void cp_wait1()  { asm volatile("cp.async.wait_group 1;"); }

__device__ __forceinline__ void ldsm4(uint32_t& r0, uint32_t& r1, uint32_t& r2, uint32_t& r3,
                                      uint32_t a) {
    asm volatile("ldmatrix.sync.aligned.m8n8.x4.shared.b16 {%0,%1,%2,%3}, [%4];"
                 : "=r"(r0), "=r"(r1), "=r"(r2), "=r"(r3) : "r"(a));
}
__device__ __forceinline__ void ldsm4t(uint32_t& r0, uint32_t& r1, uint32_t& r2, uint32_t& r3,
                                       uint32_t a) {
    asm volatile("ldmatrix.sync.aligned.m8n8.x4.trans.shared.b16 {%0,%1,%2,%3}, [%4];"
                 : "=r"(r0), "=r"(r1), "=r"(r2), "=r"(r3) : "r"(a));
}
__device__ __forceinline__ void mma16816(float* c, const uint32_t* a, uint32_t b0, uint32_t b1) {
    asm volatile(
        "mma.sync.aligned.m16n8k16.row.col.f32.f16.f16.f32 "
        "{%0,%1,%2,%3}, {%4,%5,%6,%7}, {%8,%9}, {%0,%1,%2,%3};"
        : "+f"(c[0]), "+f"(c[1]), "+f"(c[2]), "+f"(c[3])
        : "r"(a[0]), "r"(a[1]), "r"(a[2]), "r"(a[3]), "r"(b0), "r"(b1));
}

// ---------------- grouped fp16 GEMM: tile-M 128/64, split-K, 3-stage, dyn smem ----------------
struct GemmTask {
    const __half* A; const __half* B; void* C;
    int N, K, acc, ohalf;
    int blk_start, nbn, nbm, split, tm64;
};
struct GemmBatch { GemmTask t[8]; int nt; int stg; int ab; };

#define ASTRB 80      // 32 halves -> 64B, pad to 80
#define BSTRB 144     // 64 halves -> 128B, pad to 144
#define B_SB  4608    // 32 * 144
#define AB128 10240   // 128 * 80
#define AB64  5120    // 64 * 80
#define SM_MAX (3 * (AB128 + B_SB))   // 44544

__global__ __launch_bounds__(128)
void gemm_h_kernel(GemmBatch batch) {
    extern __shared__ char smem[];
    uint32_t sbase = smem_u32(smem);
    int tid = threadIdx.x;
    int warp = tid >> 5, lane = tid & 31;
    int g = lane >> 2, t = lane & 3;
    int wm = warp & 1, wn = warp >> 1;
    int STGv = batch.stg, ABv = batch.ab;

    int ti = 0;
    #pragma unroll
    for (int i = 1; i < 8; i++)
        if (i < batch.nt && (int)blockIdx.x >= batch.t[i].blk_start) ti = i;
    GemmTask T = batch.t[ti];
    int local = (int)blockIdx.x - T.blk_start;
    int per = T.nbm * T.nbn;
    int ks = local / per;
    int r2 = local % per;
    int bm = r2 / T.nbn, bn = r2 % T.nbn;
    int tm = T.tm64 ? 64 : 128;
    int row0 = bm * tm, n0 = bn * 64;

    int nchTot = (T.K + 31) / 32;
    int cpers = (nchTot + T.split - 1) / T.split;
    int cb = ks * cpers;
    int ce = cb + cpers; if (ce > nchTot) ce = nchTot;
    if (cb >= ce) return;
    int ke_el = T.K;
    int MI = T.tm64 ? 2 : 4;

    float acc[4][4][4];
    #pragma unroll
    for (int mi = 0; mi < 4; mi++)
        #pragma unroll
        for (int ni = 0; ni < 4; ni++)
            #pragma unroll
            for (int c = 0; c < 4; c++) acc[mi][ni][c] = 0.f;

    auto load_stage = [&](int ic) {
        int rel = ic - cb;
        int s = rel - (rel / 3) * 3;
        int k0 = ic * 32;
        uint32_t sa = sbase + s * STGv;
        uint32_t sb = sa + ABv;
        if (T.tm64) {
            int ar = tid >> 1, u0 = (tid & 1) * 2;
            #pragma unroll
            for (int i = 0; i < 2; i++) {
                int u = u0 + i;
                int sz = (k0 + u * 8 < ke_el) ? 16 : 0;
                cpasync16(sa + ar * ASTRB + u * 16,
                          T.A + (size_t)(row0 + ar) * T.K + k0 + u * 8, sz);
            }
        } else {
            #pragma unroll
            for (int u = 0; u < 4; u++) {
                int sz = (k0 + u * 8 < ke_el) ? 16 : 0;
                cpasync16(sa + tid * ASTRB + u * 16,
                          T.A + (size_t)(row0 + tid) * T.K + k0 + u * 8, sz);
            }
        }
        #pragma unroll
        for (int i = 0; i < 2; i++) {
            int o = tid + i * 128;
            int r = o >> 3, u = o & 7;
            int sz = ((k0 + r < ke_el) && (n0 + u * 8 < T.N)) ? 16 : 0;
            cpasync16(sb + r * BSTRB + u * 16,
                      T.B + (size_t)(k0 + r) * T.N + n0 + u * 8, sz);
        }
    };

    int wmBase = wm * (T.tm64 ? 32 : 64);
    uint32_t a_loff = (uint32_t)((wmBase + (lane & 15)) * ASTRB + (lane >> 4) * 16);
    uint32_t b_loff = (uint32_t)((lane & 15) * BSTRB + (wn * 32 + (lane >> 4) * 8) * 2);

    #pragma unroll
    for (int p = 0; p < 2; p++) {
        if (cb + p < ce) load_stage(cb + p);
        cp_commit();
    }

    for (int it = cb; it < ce; it++) {
        int rel = it - cb;
        int s = rel - (rel / 3) * 3;
        cp_wait1();
        __syncthreads();
        if (it + 2 < ce) load_stage(it + 2);
        cp_commit();

        uint32_t sa = sbase + s * STGv;
        uint32_t sb = sa + ABv;
        if (T.tm64) {
            #pragma unroll
            for (int kk = 0; kk < 2; kk++) {
                uint32_t af[2][4], bf[2][4];
                #pragma unroll
                for (int mi = 0; mi < 2; mi++)
                    ldsm4(af[mi][0], af[mi][1], af[mi][2], af[mi][3],
                          sa + a_loff + mi * (16 * ASTRB) + kk * 32);
                ldsm4t(bf[0][0], bf[0][1], bf[0][2], bf[0][3], sb + b_loff + kk * (16 * BSTRB));
                ldsm4t(bf[1][0], bf[1][1], bf[1][2], bf[1][3], sb + b_loff + kk * (16 * BSTRB) + 32);
                #pragma unroll
                for (int mi = 0; mi < 2; mi++) {
                    mma16816(acc[mi][0], af[mi], bf[0][0], bf[0][1]);
                    mma16816(acc[mi][1], af[mi], bf[0][2], bf[0][3]);
                    mma16816(acc[mi][2], af[mi], bf[1][0], bf[1][1]);
                    mma16816(acc[mi][3], af[mi], bf[1][2], bf[1][3]);
                }
            }
        } else {
            #pragma unroll
            for (int kk = 0; kk < 2; kk++) {
                uint32_t af[4][4], bf[2][4];
                #pragma unroll
                for (int mi = 0; mi < 4; mi++)
                    ldsm4(af[mi][0], af[mi][1], af[mi][2], af[mi][3],
                          sa + a_loff + mi * (16 * ASTRB) + kk * 32);
                ldsm4t(bf[0][0], bf[0][1], bf[0][2], bf[0][3], sb + b_loff + kk * (16 * BSTRB));
                ldsm4t(bf[1][0], bf[1][1], bf[1][2], bf[1][3], sb + b_loff + kk * (16 * BSTRB) + 32);
                #pragma unroll
                for (int mi = 0; mi < 4; mi++) {
                    mma16816(acc[mi][0], af[mi], bf[0][0], bf[0][1]);
                    mma16816(acc[mi][1], af[mi], bf[0][2], bf[0][3]);
                    mma16816(acc[mi][2], af[mi], bf[1][0], bf[1][1]);
                    mma16816(acc[mi][3], af[mi], bf[1][2], bf[1][3]);
                }
            }
        }
    }

    // ---- epilogue ----
    for (int mi = 0; mi < MI; mi++) {
        int r0 = row0 + wmBase + mi * 16 + g;
        #pragma unroll
        for (int ni = 0; ni < 4; ni++) {
            int cb2 = n0 + wn * 32 + ni * 8 + t * 2;
            if (cb2 >= T.N) continue;
            if (T.ohalf) {
                __half* C = (__half*)T.C;
                *(__half2*)(C + (size_t)r0 * T.N + cb2) =
                    __floats2half2_rn(acc[mi][ni][0], acc[mi][ni][1]);
                *(__half2*)(C + (size_t)(r0 + 8) * T.N + cb2) =
                    __floats2half2_rn(acc[mi][ni][2], acc[mi][ni][3]);
            } else if (T.split > 1) {
                float* C = (float*)T.C;
                atomicAdd(&C[(size_t)r0 * T.N + cb2],           acc[mi][ni][0]);
                atomicAdd(&C[(size_t)r0 * T.N + cb2 + 1],       acc[mi][ni][1]);
                atomicAdd(&C[(size_t)(r0 + 8) * T.N + cb2],     acc[mi][ni][2]);
                atomicAdd(&C[(size_t)(r0 + 8) * T.N + cb2 + 1], acc[mi][ni][3]);
            } else {
                float* C = (float*)T.C;
                if (T.acc) {
                    C[(size_t)r0 * T.N + cb2]           += acc[mi][ni][0];
                    C[(size_t)r0 * T.N + cb2 + 1]       += acc[mi][ni][1];
                    C[(size_t)(r0 + 8) * T.N + cb2]     += acc[mi][ni][2];
                    C[(size_t)(r0 + 8) * T.N + cb2 + 1] += acc[mi][ni][3];
                } else {
                    C[(size_t)r0 * T.N + cb2]           = acc[mi][ni][0];
                    C[(size_t)r0 * T.N + cb2 + 1]       = acc[mi][ni][1];
                    C[(size_t)(r0 + 8) * T.N + cb2]     = acc[mi][ni][2];
                    C[(size_t)(r0 + 8) * T.N + cb2 + 1] = acc[mi][ni][3];
                }
            }
        }
    }
}

// ---------------- fused weight conversion ----------------
struct CvtBatch {
    const float4* s[16];
    uint2* d[16];
    size_t n4[16];
};
__global__ void cvt_all_kernel(CvtBatch cb) {
    int tsk = blockIdx.y;
    const float4* s = cb.s[tsk];
    uint2* d = cb.d[tsk];
    size_t n4 = cb.n4[tsk];
    size_t i = (size_t)blockIdx.x * 256 + threadIdx.x;
    size_t stride = (size_t)gridDim.x * 256;
    for (; i < n4; i += stride) {
        float4 v = s[i];
        __half2 a = __floats2half2_rn(v.x, v.y);
        __half2 b = __floats2half2_rn(v.z, v.w);
        uint2 o;
        o.x = *(uint32_t*)&a;
        o.y = *(uint32_t*)&b;
        d[i] = o;
    }
}

// ---------------- merged RMSNorm ----------------
template<bool TOHALF>
__global__ void rms2_kernel(const float* __restrict__ x1, const float* __restrict__ w1,
                            void* __restrict__ y1, int D1, int rows1,
                            const float* __restrict__ x2, const float* __restrict__ w2,
                            void* __restrict__ y2, int D2) {
    int row = blockIdx.x;
    const float* x; const float* w; void* y; int D;
    if (row < rows1) { x = x1 + (size_t)row * D1; w = w1; y = y1; D = D1; }
    else { row -= rows1; x = x2 + (size_t)row * D2; w = w2; y = y2; D = D2; }
    __shared__ float red[256];
    float s = 0.f;
    for (int i = threadIdx.x; i < D; i += 256) { float v = x[i]; s += v * v; }
    red[threadIdx.x] = s; __syncthreads();
    for (int o = 128; o > 0; o >>= 1) {
        if (threadIdx.x < o) red[threadIdx.x] += red[threadIdx.x + o];
        __syncthreads();
    }
    float scale = rsqrtf(red[0] / D + 1e-5f);
    for (int i = threadIdx.x; i < D; i += 256) {
        float v = w[i] * x[i] * scale;
        if (TOHALF) ((__half*)y)[(size_t)row * D + i] = __float2half(v);
        else        ((float*)y)[(size_t)row * D + i] = v;
    }
}

// ---------------- coarsened RoPE ----------------
#define RP_HEADS (NH + NKV)     // 20
__global__ void rope2_kernel(__half* __restrict__ qb, __half* __restrict__ kb,
                             const int* __restrict__ pos_ids, int kRows) {
    int pair = blockIdx.x * 4 + (threadIdx.x >> 5);
    if (pair >= SS * RP_HEADS) return;
    int row = pair / RP_HEADS;
    int h = pair - row * RP_HEADS;
    int j = threadIdx.x & 31;
    __half* p;
    if (h < NH) p = qb + (size_t)row * QW + h * 64;
    else {
        if (row >= kRows) return;
        p = kb + (size_t)row * KW + (h - NH) * 64;
    }
    float pos = (float)pos_ids[row];
    float ts = powf(10000.f, (float)j / 32.f);
    float rad = pos / ts;
    float sn = sinf(rad), cs = cosf(rad);
    float x1 = __half2float(p[j]), x2 = __half2float(p[j + 32]);
    p[j]      = __float2half(x1 * cs - x2 * sn);
    p[j + 32] = __float2half(x2 * cs + x1 * sn);
}

// ---------------- GQA-fused attention ----------------
// mode 0: dense, Lk keys. mode 1: joint ragged (vlm rows see PL, expert causal).
// mode 2: merged odd layer — blockIdx.y<NKV: self-attn (Q,K,V,O, PL rows);
//         else: cross-attn (Q2,K2,V2,O2, EL rows), both Lk=PL dense.
__global__ void attn_kernel(const __half* __restrict__ Q, const __half* __restrict__ K,
                            const __half* __restrict__ V, __half* __restrict__ O,
                            int Lk, int mode,
                            const __half* __restrict__ Q2, const __half* __restrict__ K2,
                            const __half* __restrict__ V2, __half* __restrict__ O2) {
    int q = blockIdx.x, kvh = blockIdx.y;
    const __half *Qp = Q, *Kp = K, *Vp = V;
    __half* Op = O;
    if (mode == 2 && kvh >= NKV) {
        if (q >= EL) return;
        kvh -= NKV;
        Qp = Q2; Kp = K2; Vp = V2; Op = O2;
    }
    int tid = threadIdx.x;            // 128
    __shared__ float q3[192];
    __shared__ float sc[3][SS];
    __shared__ float red[128];
    __shared__ float mm[3], invs[3];
    __shared__ float pv[128][6];

    int kmax = (mode == 1) ? ((q < PL) ? PL : (q + 1)) : Lk;

    for (int i = tid; i < 192; i += 128) {
        int j = i >> 6, d = i & 63;
        q3[i] = __half2float(Qp[(size_t)q * QW + (kvh * 3 + j) * 64 + d]);
    }
    __syncthreads();

    float pm0 = -3.0e38f, pm1 = -3.0e38f, pm2 = -3.0e38f;
    for (int k = tid; k < kmax; k += 128) {
        const __half2* kp = (const __half2*)(Kp + (size_t)k * KW + kvh * 64);
        float d0 = 0.f, d1 = 0.f, d2 = 0.f;
        #pragma unroll
        for (int i = 0; i < 32; i++) {
            float2 f = __half22float2(kp[i]);
            d0 += q3[2*i] * f.x + q3[2*i+1] * f.y;
            d1 += q3[64+2*i] * f.x + q3[64+2*i+1] * f.y;
            d2 += q3[128+2*i] * f.x + q3[128+2*i+1] * f.y;
        }
        float s0 = d0 * 0.125f, s1 = d1 * 0.125f, s2 = d2 * 0.125f;
        sc[0][k] = s0; sc[1][k] = s1; sc[2][k] = s2;
        pm0 = fmaxf(pm0, s0); pm1 = fmaxf(pm1, s1); pm2 = fmaxf(pm2, s2);
    }
    float pms[3] = {pm0, pm1, pm2};
    for (int j = 0; j < 3; j++) {
        __syncthreads();
        red[tid] = pms[j]; __syncthreads();
        for (int o = 64; o > 0; o >>= 1) {
            if (tid < o) red[tid] = fmaxf(red[tid], red[tid + o]);
            __syncthreads();
        }
        if (tid == 0) mm[j] = red[0];
    }
    __syncthreads();

    float ps0 = 0.f, ps1 = 0.f, ps2 = 0.f;
    float m0 = mm[0], m1 = mm[1], m2 = mm[2];
    for (int k = tid; k < kmax; k += 128) {
        float e0 = __expf(sc[0][k] - m0); sc[0][k] = e0; ps0 += e0;
        float e1 = __expf(sc[1][k] - m1); sc[1][k] = e1; ps1 += e1;
        float e2 = __expf(sc[2][k] - m2); sc[2][k] = e2; ps2 += e2;
    }
    float pss[3] = {ps0, ps1, ps2};
    for (int j = 0; j < 3; j++) {
        __syncthreads();
        red[tid] = pss[j]; __syncthreads();
        for (int o = 64; o > 0; o >>= 1) {
            if (tid < o) red[tid] += red[tid + o];
            __syncthreads();
        }
        if (tid == 0) invs[j] = 1.f / red[0];
    }
    __syncthreads();

    {
        int quar = tid >> 5, h2 = tid & 31;
        int Lq = kmax >> 2;
        int kb = quar * Lq;
        int kend = (quar == 3) ? kmax : (kb + Lq);
        float a0x = 0.f, a0y = 0.f, a1x = 0.f, a1y = 0.f, a2x = 0.f, a2y = 0.f;
        const __half2* vp = (const __half2*)(Vp + kvh * 64) + h2;
        for (int k = kb; k < kend; k++) {
            float2 f = __half22float2(vp[(size_t)k * (KW / 2)]);
            float s0 = sc[0][k], s1 = sc[1][k], s2 = sc[2][k];
            a0x += s0 * f.x; a0y += s0 * f.y;
            a1x += s1 * f.x; a1y += s1 * f.y;
            a2x += s2 * f.x; a2y += s2 * f.y;
        }
        pv[tid][0] = a0x; pv[tid][1] = a0y;
        pv[tid][2] = a1x; pv[tid][3] = a1y;
        pv[tid][4] = a2x; pv[tid][5] = a2y;
    }
    __syncthreads();
    if (tid < 32) {
        #pragma unroll
        for (int j = 0; j < 3; j++) {
            float rx = 0.f, ry = 0.f;
            #pragma unroll
            for (int qq = 0; qq < 4; qq++) {
                rx += pv[qq * 32 + tid][j * 2];
                ry += pv[qq * 32 + tid][j * 2 + 1];
            }
            __half2* op = (__half2*)(Op + (size_t)q * QW + (kvh * 3 + j) * 64);
            op[tid] = __floats2half2_rn(rx * invs[j], ry * invs[j]);
        }
    }
}

// ---------------- merged silu ----------------
__global__ void silu2_kernel(const float* __restrict__ g1, const float* __restrict__ u1,
                             __half* __restrict__ o1, int n1,
                             const float* __restrict__ g2, const float* __restrict__ u2,
                             __half* __restrict__ o2, int n2) {
    int i = blockIdx.x * 256 + threadIdx.x;
    if (i < n1) {
        float x = g1[i];
        o1[i] = __float2half((x / (1.f + __expf(-x))) * u1[i]);
    } else if (i - n1 < n2) {
        int j = i - n1;
        float x = g2[j];
        o2[j] = __float2half((x / (1.f + __expf(-x))) * u2[j]);
    }
}

// ---------------- host-side grouped-gemm builder ----------------
static inline void batch_init(GemmBatch& b, int& blk) { b.nt = 0; blk = 0; }
static inline void batch_add(GemmBatch& b, int& blk,
                             const __half* A, const __half* B, void* C,
                             int M, int N, int K, int acc, int ohalf,
                             int split = 1, int tm64 = 0) {
    GemmTask& T = b.t[b.nt++];
    T.A = A; T.B = B; T.C = C; T.N = N; T.K = K; T.acc = acc; T.ohalf = ohalf;
    T.tm64 = tm64;
    T.nbn = (N + 63) / 64;
    T.nbm = M / (tm64 ? 64 : 128);
    T.split = split;
    T.blk_start = blk;
    blk += T.nbn * T.nbm * split;
}
static inline void batch_go(GemmBatch& b, int blk) {
    int anyM128 = 0;
    for (int i = 0; i < b.nt; i++) if (!b.t[i].tm64) anyM128 = 1;
    b.ab = anyM128 ? AB128 : AB64;
    b.stg = b.ab + B_SB;
    gemm_h_kernel<<<blk, 128, 3 * b.stg>>>(b);
}

extern "C" void kernel_launch(void* const* d_in, const int* in_sizes, int n_in,
                              void* d_out, int out_size) {
    const float* in_vlm = (const float*)d_in[0];
    const float* in_exp = (const float*)d_in[1];
    const float* f_vq   = (const float*)d_in[2];
    const float* f_vk   = (const float*)d_in[3];
    const float* f_vv   = (const float*)d_in[4];
    const float* f_vo   = (const float*)d_in[5];
    const float* w_vln1 = (const float*)d_in[6];
    const float* w_vln2 = (const float*)d_in[7];
    const float* f_vg   = (const float*)d_in[8];
    const float* f_vu   = (const float*)d_in[9];
    const float* f_vd   = (const float*)d_in[10];
    const float* w_vfn  = (const float*)d_in[11];
    const float* f_eq   = (const float*)d_in[12];
    const float* f_eks  = (const float*)d_in[13];
    const float* f_evs  = (const float*)d_in[14];
    const float* f_ekc  = (const float*)d_in[15];
    const float* f_evc  = (const float*)d_in[16];
    const float* f_eo   = (const float*)d_in[17];
    const float* w_eln1 = (const float*)d_in[18];
    const float* w_eln2 = (const float*)d_in[19];
    const float* f_eg   = (const float*)d_in[20];
    const float* f_eu   = (const float*)d_in[21];
    const float* f_ed   = (const float*)d_in[22];
    const float* w_efn  = (const float*)d_in[23];
    const int*   pos_ids = (const int*)d_in[24];
    float* out = (float*)d_out;

    cudaFuncSetAttribute(gemm_h_kernel,
                         cudaFuncAttributeMaxDynamicSharedMemorySize, SM_MAX);

    __half* wh;
    cudaGetSymbolAddress((void**)&wh, g_wh);
    float *vlm, *exps, *m1, *m2, *e1, *e2;
    __half *hv, *he, *q, *k, *v, *ke, *ve, *att, *m2h, *e2h;
    cudaGetSymbolAddress((void**)&vlm, g_vlm);
    cudaGetSymbolAddress((void**)&exps, g_exp);
    cudaGetSymbolAddress((void**)&m1, g_m1);
    cudaGetSymbolAddress((void**)&m2, g_m2);
    cudaGetSymbolAddress((void**)&e1, g_e1);
    cudaGetSymbolAddress((void**)&e2, g_e2);
    cudaGetSymbolAddress((void**)&hv, h_hv);
    cudaGetSymbolAddress((void**)&he, h_he);
    cudaGetSymbolAddress((void**)&q,  h_q);
    cudaGetSymbolAddress((void**)&k,  h_k);
    cudaGetSymbolAddress((void**)&v,  h_v);
    cudaGetSymbolAddress((void**)&ke, h_ke);
    cudaGetSymbolAddress((void**)&ve, h_ve);
    cudaGetSymbolAddress((void**)&att, h_att);
    cudaGetSymbolAddress((void**)&m2h, h_m2);
    cudaGetSymbolAddress((void**)&e2h, h_e2);

    // ---- convert all weights to half in ONE launch ----
    {
        CvtBatch cb;
        const float* srcs[16] = {f_vq, f_vk, f_vv, f_vo, f_vg, f_vu, f_vd, f_eq,
                                 f_eks, f_evs, f_ekc, f_evc, f_eo, f_eg, f_eu, f_ed};
        size_t offs[16] = {O_VQ, O_VK, O_VV, O_VO, O_VG, O_VU, O_VD, O_EQ,
                           O_EKS, O_EVS, O_EKC, O_EVC, O_EO, O_EG, O_EU, O_ED};
        size_t ns[16] = {N_VQ, N_VK, N_VV, N_VO, N_VG, N_VU, N_VD, N_EQ,
                         N_EKS, N_EVS, N_EKC, N_EVC, N_EO, N_EG, N_EU, N_ED};
        for (int i = 0; i < 16; i++) {
            cb.s[i] = (const float4*)srcs[i];
            cb.d[i] = (uint2*)(wh + offs[i]);
            cb.n4[i] = ns[i] / 4;
        }
        cvt_all_kernel<<<dim3(160, 16), 256>>>(cb);
    }

    cudaMemcpyAsync(vlm,  in_vlm, (size_t)PL * TH * sizeof(float), cudaMemcpyDeviceToDevice);
    cudaMemcpyAsync(exps, in_exp, (size_t)EL * EH * sizeof(float), cudaMemcpyDeviceToDevice);

    GemmBatch b; int blk;
    const int ropeBlocks = (SS * RP_HEADS + 3) / 4;

    for (int li = 0; li < L_LAYERS; li++) {
        const __half* vq  = wh + O_VQ  + (size_t)li * TH * QW;
        const __half* vk  = wh + O_VK  + (size_t)li * TH * KW;
        const __half* vv  = wh + O_VV  + (size_t)li * TH * KW;
        const __half* vo  = wh + O_VO  + (size_t)li * QW * TH;
        const __half* vg  = wh + O_VG  + (size_t)li * TH * TI;
        const __half* vu  = wh + O_VU  + (size_t)li * TH * TI;
        const __half* vd  = wh + O_VD  + (size_t)li * TI * TH;
        const __half* eq  = wh + O_EQ  + (size_t)li * EH * QW;
        const __half* eo  = wh + O_EO  + (size_t)li * QW * EH;
        const __half* eg  = wh + O_EG  + (size_t)li * EH * EI;
        const __half* eu  = wh + O_EU  + (size_t)li * EH * EI;
        const __half* ed  = wh + O_ED  + (size_t)li * EI * EH;

        rms2_kernel<true><<<PL + EL, 256>>>(vlm, w_vln1 + (size_t)li * TH, hv, TH, PL,
                                            exps, w_eln1 + (size_t)li * EH, he, EH);

        if (li % 2 == 0) {
            const __half* eks = wh + O_EKS + (size_t)(li / 2) * EH * KW;
            const __half* evs = wh + O_EVS + (size_t)(li / 2) * EH * KW;
            batch_init(b, blk);
            batch_add(b, blk, hv, vq,  q,                    PL, QW, TH, 0, 1, 1, 1);
            batch_add(b, blk, hv, vk,  k,                    PL, KW, TH, 0, 1, 1, 1);
            batch_add(b, blk, hv, vv,  v,                    PL, KW, TH, 0, 1, 1, 1);
            batch_add(b, blk, he, eq,  q + (size_t)PL * QW,  EL, QW, EH, 0, 1, 1, 1);
            batch_add(b, blk, he, eks, k + (size_t)PL * KW,  EL, KW, EH, 0, 1, 1, 1);
            batch_add(b, blk, he, evs, v + (size_t)PL * KW,  EL, KW, EH, 0, 1, 1, 1);
            batch_go(b, blk);
            rope2_kernel<<<ropeBlocks, 128>>>(q, k, pos_ids, SS);
            attn_kernel<<<dim3(SS, NKV), 128>>>(q, k, v, att, SS, 1,
                                                nullptr, nullptr, nullptr, nullptr);
        } else {
            const __half* ekc = wh + O_EKC + (size_t)(li / 2) * KW * KW;
            const __half* evc = wh + O_EVC + (size_t)(li / 2) * KW * KW;
            batch_init(b, blk);
            batch_add(b, blk, hv, vq, q,                   PL, QW, TH, 0, 1, 1, 1);
            batch_add(b, blk, hv, vk, k,                   PL, KW, TH, 0, 1, 1, 1);
            batch_add(b, blk, hv, vv, v,                   PL, KW, TH, 0, 1, 1, 1);
            batch_add(b, blk, he, eq, q + (size_t)PL * QW, EL, QW, EH, 0, 1, 1, 1);
            batch_go(b, blk);
            rope2_kernel<<<ropeBlocks, 128>>>(q, k, pos_ids, PL);
            batch_init(b, blk);
            batch_add(b, blk, k, ekc, ke, PL, KW, KW, 0, 1, 1, 1);
            batch_add(b, blk, v, evc, ve, PL, KW, KW, 0, 1, 1, 1);
            batch_go(b, blk);
            // merged self + cross attention in one launch
            attn_kernel<<<dim3(PL, 2 * NKV), 128>>>(q, k, v, att, PL, 2,
                                                    q + (size_t)PL * QW, ke, ve,
                                                    att + (size_t)PL * QW);
        }

        // ---- wo: M64 + split-K (576 blocks) ----
        batch_init(b, blk);
        batch_add(b, blk, att,                    vo, vlm,  PL, TH, QW, 1, 0, 4, 1);
        batch_add(b, blk, att + (size_t)PL * QW,  eo, exps, EL, EH, QW, 1, 0, 4, 1);
        batch_go(b, blk);

        rms2_kernel<true><<<PL + EL, 256>>>(vlm, w_vln2 + (size_t)li * TH, hv, TH, PL,
                                            exps, w_eln2 + (size_t)li * EH, he, EH);

        // ---- gate + up: vlm M128 single wave, exp M64 ----
        batch_init(b, blk);
        batch_add(b, blk, hv, vg, m1, PL, TI, TH, 0, 0, 1, 0);
        batch_add(b, blk, hv, vu, m2, PL, TI, TH, 0, 0, 1, 0);
        batch_add(b, blk, he, eg, e1, EL, EI, EH, 0, 0, 1, 1);
        batch_add(b, blk, he, eu, e2, EL, EI, EH, 0, 0, 1, 1);
        batch_go(b, blk);

        silu2_kernel<<<(PL * TI + EL * EI + 255) / 256, 256>>>(
            m1, m2, m2h, PL * TI, e1, e2, e2h, EL * EI);

        // ---- down: M64 + split-K (672 blocks) ----
        batch_init(b, blk);
        batch_add(b, blk, m2h, vd, vlm,  PL, TH, TI, 1, 0, 4, 1);
        batch_add(b, blk, e2h, ed, exps, EL, EH, EI, 1, 0, 4, 1);
        batch_go(b, blk);
    }

    // final norms -> fp32 output (merged)
    rms2_kernel<false><<<PL + EL, 256>>>(vlm, w_vfn, out, TH, PL,
                                         exps, w_efn, out + (size_t)PL * TH, EH);
}

// round 15
// speedup vs baseline: 1.0742x; 1.0742x over previous
// R14: revert to R12 config (measured best); keep ONLY merged odd attention + 3-wide attn reductions.
#include <cuda_runtime.h>
#include <cuda_fp16.h>
#include <math.h>
#include <stdint.h>

#define L_LAYERS 16
#define HD 64
#define NH 15
#define NKV 5
#define TH 960
#define TI 2560
#define EH 720
#define EI 2048
#define PL 512
#define EL 128
#define SS 640
#define QW (NH*HD)   // 960
#define KW (NKV*HD)  // 320

// ---------------- weight half cache ----------------
#define N_VQ  ((size_t)L_LAYERS*TH*QW)
#define N_VK  ((size_t)L_LAYERS*TH*KW)
#define N_VV  ((size_t)L_LAYERS*TH*KW)
#define N_VO  ((size_t)L_LAYERS*QW*TH)
#define N_VG  ((size_t)L_LAYERS*TH*TI)
#define N_VU  ((size_t)L_LAYERS*TH*TI)
#define N_VD  ((size_t)L_LAYERS*TI*TH)
#define N_EQ  ((size_t)L_LAYERS*EH*QW)
#define N_EKS ((size_t)(L_LAYERS/2)*EH*KW)
#define N_EVS ((size_t)(L_LAYERS/2)*EH*KW)
#define N_EKC ((size_t)(L_LAYERS/2)*KW*KW)
#define N_EVC ((size_t)(L_LAYERS/2)*KW*KW)
#define N_EO  ((size_t)L_LAYERS*QW*EH)
#define N_EG  ((size_t)L_LAYERS*EH*EI)
#define N_EU  ((size_t)L_LAYERS*EH*EI)
#define N_ED  ((size_t)L_LAYERS*EI*EH)

#define O_VQ  ((size_t)0)
#define O_VK  (O_VQ + N_VQ)
#define O_VV  (O_VK + N_VK)
#define O_VO  (O_VV + N_VV)
#define O_VG  (O_VO + N_VO)
#define O_VU  (O_VG + N_VG)
#define O_VD  (O_VU + N_VU)
#define O_EQ  (O_VD + N_VD)
#define O_EKS (O_EQ + N_EQ)
#define O_EVS (O_EKS + N_EKS)
#define O_EKC (O_EVS + N_EVS)
#define O_EVC (O_EKC + N_EKC)
#define O_EO  (O_EVC + N_EVC)
#define O_EG  (O_EO + N_EO)
#define O_EU  (O_EG + N_EG)
#define O_ED  (O_EU + N_EU)
#define W_TOTAL (O_ED + N_ED)

__device__ __align__(128) __half g_wh[W_TOTAL];

// ---------------- activation / residual scratch ----------------
__device__ __align__(128) float  g_vlm[PL*TH];
__device__ __align__(128) float  g_exp[EL*EH];
__device__ __align__(128) float  g_m1 [PL*TI];
__device__ __align__(128) float  g_m2 [PL*TI];
__device__ __align__(128) float  g_e1 [EL*EI];
__device__ __align__(128) float  g_e2 [EL*EI];
__device__ __align__(128) __half h_hv [PL*TH];
__device__ __align__(128) __half h_he [EL*EH];
__device__ __align__(128) __half h_q  [SS*QW];
__device__ __align__(128) __half h_k  [SS*KW];
__device__ __align__(128) __half h_v  [SS*KW];
__device__ __align__(128) __half h_ke [PL*KW];
__device__ __align__(128) __half h_ve [PL*KW];
__device__ __align__(128) __half h_att[SS*QW];
__device__ __align__(128) __half h_m2 [PL*TI];
__device__ __align__(128) __half h_e2 [EL*EI];

// ---------------- PTX helpers ----------------
__device__ __forceinline__ uint32_t smem_u32(const void* p) {
    uint32_t a;
    asm("{ .reg .u64 t; cvta.to.shared.u64 t, %1; cvt.u32.u64 %0, t; }" : "=r"(a) : "l"(p));
    return a;
}
__device__ __forceinline__ void cpasync16(uint32_t s, const void* g, int sz) {
    asm volatile("cp.async.ca.shared.global [%0], [%1], 16, %2;" :: "r"(s), "l"(g), "r"(sz));
}
__device__ __forceinline__ void cp_commit() { asm volatile("cp.async.commit_group;"); }
__device__ __forceinline__ void cp_wait1()  { asm volatile("cp.async.wait_group 1;"); }

__device__ __forceinline__ void ldsm4(uint32_t& r0, uint32_t& r1, uint32_t& r2, uint32_t& r3,
                                      uint32_t a) {
    asm volatile("ldmatrix.sync.aligned.m8n8.x4.shared.b16 {%0,%1,%2,%3}, [%4];"
                 : "=r"(r0), "=r"(r1), "=r"(r2), "=r"(r3) : "r"(a));
}
__device__ __forceinline__ void ldsm4t(uint32_t& r0, uint32_t& r1, uint32_t& r2, uint32_t& r3,
                                       uint32_t a) {
    asm volatile("ldmatrix.sync.aligned.m8n8.x4.trans.shared.b16 {%0,%1,%2,%3}, [%4];"
                 : "=r"(r0), "=r"(r1), "=r"(r2), "=r"(r3) : "r"(a));
}
__device__ __forceinline__ void mma16816(float* c, const uint32_t* a, uint32_t b0, uint32_t b1) {
    asm volatile(
        "mma.sync.aligned.m16n8k16.row.col.f32.f16.f16.f32 "
        "{%0,%1,%2,%3}, {%4,%5,%6,%7}, {%8,%9}, {%0,%1,%2,%3};"
        : "+f"(c[0]), "+f"(c[1]), "+f"(c[2]), "+f"(c[3])
        : "r"(a[0]), "r"(a[1]), "r"(a[2]), "r"(a[3]), "r"(b0), "r"(b1));
}

// ---------------- grouped fp16 GEMM: per-task tile-M (128/64), split-K, 3-stage ----------------
struct GemmTask {
    const __half* A; const __half* B; void* C;
    int N, K, acc, ohalf;
    int blk_start, nbn, nbm, split, tm64;
};
struct GemmBatch { GemmTask t[8]; int nt; };

#define ASTRB 80      // 32 halves -> 64B, pad to 80
#define BSTRB 144     // 64 halves -> 128B, pad to 144
#define A_SB  10240   // 128 * 80 (M64 uses first half)
#define B_SB  4608    // 32 * 144
#define STG   (A_SB + B_SB)     // 14848
#define SM_TOT (3 * STG)        // 44544

__global__ __launch_bounds__(128)
void gemm_h_kernel(GemmBatch batch) {
    extern __shared__ char smem[];
    uint32_t sbase = smem_u32(smem);
    int tid = threadIdx.x;
    int warp = tid >> 5, lane = tid & 31;
    int g = lane >> 2, t = lane & 3;
    int wm = warp & 1, wn = warp >> 1;

    int ti = 0;
    #pragma unroll
    for (int i = 1; i < 8; i++)
        if (i < batch.nt && (int)blockIdx.x >= batch.t[i].blk_start) ti = i;
    GemmTask T = batch.t[ti];
    int local = (int)blockIdx.x - T.blk_start;
    int per = T.nbm * T.nbn;
    int ks = local / per;
    int r2 = local % per;
    int bm = r2 / T.nbn, bn = r2 % T.nbn;
    int tm = T.tm64 ? 64 : 128;
    int row0 = bm * tm, n0 = bn * 64;

    int nchTot = (T.K + 31) / 32;
    int cpers = (nchTot + T.split - 1) / T.split;
    int cb = ks * cpers;
    int ce = cb + cpers; if (ce > nchTot) ce = nchTot;
    if (cb >= ce) return;
    int ke_el = T.K;
    int MI = T.tm64 ? 2 : 4;

    float acc[4][4][4];
    #pragma unroll
    for (int mi = 0; mi < 4; mi++)
        #pragma unroll
        for (int ni = 0; ni < 4; ni++)
            #pragma unroll
            for (int c = 0; c < 4; c++) acc[mi][ni][c] = 0.f;

    auto load_stage = [&](int ic) {
        int rel = ic - cb;
        int s = rel - (rel / 3) * 3;
        int k0 = ic * 32;
        uint32_t sa = sbase + s * STG;
        uint32_t sb = sa + A_SB;
        if (T.tm64) {
            int ar = tid >> 1, u0 = (tid & 1) * 2;
            #pragma unroll
            for (int i = 0; i < 2; i++) {
                int u = u0 + i;
                int sz = (k0 + u * 8 < ke_el) ? 16 : 0;
                cpasync16(sa + ar * ASTRB + u * 16,
                          T.A + (size_t)(row0 + ar) * T.K + k0 + u * 8, sz);
            }
        } else {
            #pragma unroll
            for (int u = 0; u < 4; u++) {
                int sz = (k0 + u * 8 < ke_el) ? 16 : 0;
                cpasync16(sa + tid * ASTRB + u * 16,
                          T.A + (size_t)(row0 + tid) * T.K + k0 + u * 8, sz);
            }
        }
        #pragma unroll
        for (int i = 0; i < 2; i++) {
            int o = tid + i * 128;
            int r = o >> 3, u = o & 7;
            int sz = ((k0 + r < ke_el) && (n0 + u * 8 < T.N)) ? 16 : 0;
            cpasync16(sb + r * BSTRB + u * 16,
                      T.B + (size_t)(k0 + r) * T.N + n0 + u * 8, sz);
        }
    };

    int wmBase = wm * (T.tm64 ? 32 : 64);
    uint32_t a_loff = (uint32_t)((wmBase + (lane & 15)) * ASTRB + (lane >> 4) * 16);
    uint32_t b_loff = (uint32_t)((lane & 15) * BSTRB + (wn * 32 + (lane >> 4) * 8) * 2);

    #pragma unroll
    for (int p = 0; p < 2; p++) {
        if (cb + p < ce) load_stage(cb + p);
        cp_commit();
    }

    for (int it = cb; it < ce; it++) {
        int rel = it - cb;
        int s = rel - (rel / 3) * 3;
        cp_wait1();
        __syncthreads();
        if (it + 2 < ce) load_stage(it + 2);
        cp_commit();

        uint32_t sa = sbase + s * STG;
        uint32_t sb = sa + A_SB;
        if (T.tm64) {
            #pragma unroll
            for (int kk = 0; kk < 2; kk++) {
                uint32_t af[2][4], bf[2][4];
                #pragma unroll
                for (int mi = 0; mi < 2; mi++)
                    ldsm4(af[mi][0], af[mi][1], af[mi][2], af[mi][3],
                          sa + a_loff + mi * (16 * ASTRB) + kk * 32);
                ldsm4t(bf[0][0], bf[0][1], bf[0][2], bf[0][3], sb + b_loff + kk * (16 * BSTRB));
                ldsm4t(bf[1][0], bf[1][1], bf[1][2], bf[1][3], sb + b_loff + kk * (16 * BSTRB) + 32);
                #pragma unroll
                for (int mi = 0; mi < 2; mi++) {
                    mma16816(acc[mi][0], af[mi], bf[0][0], bf[0][1]);
                    mma16816(acc[mi][1], af[mi], bf[0][2], bf[0][3]);
                    mma16816(acc[mi][2], af[mi], bf[1][0], bf[1][1]);
                    mma16816(acc[mi][3], af[mi], bf[1][2], bf[1][3]);
                }
            }
        } else {
            #pragma unroll
            for (int kk = 0; kk < 2; kk++) {
                uint32_t af[4][4], bf[2][4];
                #pragma unroll
                for (int mi = 0; mi < 4; mi++)
                    ldsm4(af[mi][0], af[mi][1], af[mi][2], af[mi][3],
                          sa + a_loff + mi * (16 * ASTRB) + kk * 32);
                ldsm4t(bf[0][0], bf[0][1], bf[0][2], bf[0][3], sb + b_loff + kk * (16 * BSTRB));
                ldsm4t(bf[1][0], bf[1][1], bf[1][2], bf[1][3], sb + b_loff + kk * (16 * BSTRB) + 32);
                #pragma unroll
                for (int mi = 0; mi < 4; mi++) {
                    mma16816(acc[mi][0], af[mi], bf[0][0], bf[0][1]);
                    mma16816(acc[mi][1], af[mi], bf[0][2], bf[0][3]);
                    mma16816(acc[mi][2], af[mi], bf[1][0], bf[1][1]);
                    mma16816(acc[mi][3], af[mi], bf[1][2], bf[1][3]);
                }
            }
        }
    }

    // ---- epilogue ----
    for (int mi = 0; mi < MI; mi++) {
        int r0 = row0 + wmBase + mi * 16 + g;
        #pragma unroll
        for (int ni = 0; ni < 4; ni++) {
            int cb2 = n0 + wn * 32 + ni * 8 + t * 2;
            if (cb2 >= T.N) continue;
            if (T.ohalf) {
                __half* C = (__half*)T.C;
                *(__half2*)(C + (size_t)r0 * T.N + cb2) =
                    __floats2half2_rn(acc[mi][ni][0], acc[mi][ni][1]);
                *(__half2*)(C + (size_t)(r0 + 8) * T.N + cb2) =
                    __floats2half2_rn(acc[mi][ni][2], acc[mi][ni][3]);
            } else if (T.split > 1) {
                float* C = (float*)T.C;
                atomicAdd(&C[(size_t)r0 * T.N + cb2],           acc[mi][ni][0]);
                atomicAdd(&C[(size_t)r0 * T.N + cb2 + 1],       acc[mi][ni][1]);
                atomicAdd(&C[(size_t)(r0 + 8) * T.N + cb2],     acc[mi][ni][2]);
                atomicAdd(&C[(size_t)(r0 + 8) * T.N + cb2 + 1], acc[mi][ni][3]);
            } else {
                float* C = (float*)T.C;
                if (T.acc) {
                    C[(size_t)r0 * T.N + cb2]           += acc[mi][ni][0];
                    C[(size_t)r0 * T.N + cb2 + 1]       += acc[mi][ni][1];
                    C[(size_t)(r0 + 8) * T.N + cb2]     += acc[mi][ni][2];
                    C[(size_t)(r0 + 8) * T.N + cb2 + 1] += acc[mi][ni][3];
                } else {
                    C[(size_t)r0 * T.N + cb2]           = acc[mi][ni][0];
                    C[(size_t)r0 * T.N + cb2 + 1]       = acc[mi][ni][1];
                    C[(size_t)(r0 + 8) * T.N + cb2]     = acc[mi][ni][2];
                    C[(size_t)(r0 + 8) * T.N + cb2 + 1] = acc[mi][ni][3];
                }
            }
        }
    }
}

// ---------------- fused weight conversion ----------------
struct CvtBatch {
    const float4* s[16];
    uint2* d[16];
    size_t n4[16];
};
__global__ void cvt_all_kernel(CvtBatch cb) {
    int tsk = blockIdx.y;
    const float4* s = cb.s[tsk];
    uint2* d = cb.d[tsk];
    size_t n4 = cb.n4[tsk];
    size_t i = (size_t)blockIdx.x * 256 + threadIdx.x;
    size_t stride = (size_t)gridDim.x * 256;
    for (; i < n4; i += stride) {
        float4 v = s[i];
        __half2 a = __floats2half2_rn(v.x, v.y);
        __half2 b = __floats2half2_rn(v.z, v.w);
        uint2 o;
        o.x = *(uint32_t*)&a;
        o.y = *(uint32_t*)&b;
        d[i] = o;
    }
}

// ---------------- merged RMSNorm ----------------
template<bool TOHALF>
__global__ void rms2_kernel(const float* __restrict__ x1, const float* __restrict__ w1,
                            void* __restrict__ y1, int D1, int rows1,
                            const float* __restrict__ x2, const float* __restrict__ w2,
                            void* __restrict__ y2, int D2) {
    int row = blockIdx.x;
    const float* x; const float* w; void* y; int D;
    if (row < rows1) { x = x1 + (size_t)row * D1; w = w1; y = y1; D = D1; }
    else { row -= rows1; x = x2 + (size_t)row * D2; w = w2; y = y2; D = D2; }
    __shared__ float red[256];
    float s = 0.f;
    for (int i = threadIdx.x; i < D; i += 256) { float v = x[i]; s += v * v; }
    red[threadIdx.x] = s; __syncthreads();
    for (int o = 128; o > 0; o >>= 1) {
        if (threadIdx.x < o) red[threadIdx.x] += red[threadIdx.x + o];
        __syncthreads();
    }
    float scale = rsqrtf(red[0] / D + 1e-5f);
    for (int i = threadIdx.x; i < D; i += 256) {
        float v = w[i] * x[i] * scale;
        if (TOHALF) ((__half*)y)[(size_t)row * D + i] = __float2half(v);
        else        ((float*)y)[(size_t)row * D + i] = v;
    }
}

// ---------------- coarsened RoPE ----------------
#define RP_HEADS (NH + NKV)     // 20
__global__ void rope2_kernel(__half* __restrict__ qb, __half* __restrict__ kb,
                             const int* __restrict__ pos_ids, int kRows) {
    int pair = blockIdx.x * 4 + (threadIdx.x >> 5);
    if (pair >= SS * RP_HEADS) return;
    int row = pair / RP_HEADS;
    int h = pair - row * RP_HEADS;
    int j = threadIdx.x & 31;
    __half* p;
    if (h < NH) p = qb + (size_t)row * QW + h * 64;
    else {
        if (row >= kRows) return;
        p = kb + (size_t)row * KW + (h - NH) * 64;
    }
    float pos = (float)pos_ids[row];
    float ts = powf(10000.f, (float)j / 32.f);
    float rad = pos / ts;
    float sn = sinf(rad), cs = cosf(rad);
    float x1 = __half2float(p[j]), x2 = __half2float(p[j + 32]);
    p[j]      = __float2half(x1 * cs - x2 * sn);
    p[j + 32] = __float2half(x2 * cs + x1 * sn);
}

// ---------------- GQA-fused attention (ragged bound; merged odd mode) ----------------
// mode 0: dense Lk. mode 1: joint ragged. mode 2: y<NKV self PL; y>=NKV cross (Q2..O2), EL rows.
__global__ void attn_kernel(const __half* __restrict__ Q, const __half* __restrict__ K,
                            const __half* __restrict__ V, __half* __restrict__ O,
                            int Lk, int mode,
                            const __half* __restrict__ Q2, const __half* __restrict__ K2,
                            const __half* __restrict__ V2, __half* __restrict__ O2) {
    int q = blockIdx.x, kvh = blockIdx.y;
    const __half *Qp = Q, *Kp = K, *Vp = V;
    __half* Op = O;
    if (mode == 2 && kvh >= NKV) {
        if (q >= EL) return;
        kvh -= NKV;
        Qp = Q2; Kp = K2; Vp = V2; Op = O2;
    }
    int tid = threadIdx.x;            // 128
    __shared__ float q3[192];
    __shared__ float sc[3][SS];
    __shared__ float red3[128][3];
    __shared__ float mm[3], invs[3];
    __shared__ float pv[128][6];

    int kmax = (mode == 1) ? ((q < PL) ? PL : (q + 1)) : Lk;

    for (int i = tid; i < 192; i += 128) {
        int j = i >> 6, d = i & 63;
        q3[i] = __half2float(Qp[(size_t)q * QW + (kvh * 3 + j) * 64 + d]);
    }
    __syncthreads();

    float pm0 = -3.0e38f, pm1 = -3.0e38f, pm2 = -3.0e38f;
    for (int k = tid; k < kmax; k += 128) {
        const __half2* kp = (const __half2*)(Kp + (size_t)k * KW + kvh * 64);
        float d0 = 0.f, d1 = 0.f, d2 = 0.f;
        #pragma unroll
        for (int i = 0; i < 32; i++) {
            float2 f = __half22float2(kp[i]);
            d0 += q3[2*i] * f.x + q3[2*i+1] * f.y;
            d1 += q3[64+2*i] * f.x + q3[64+2*i+1] * f.y;
            d2 += q3[128+2*i] * f.x + q3[128+2*i+1] * f.y;
        }
        float s0 = d0 * 0.125f, s1 = d1 * 0.125f, s2 = d2 * 0.125f;
        sc[0][k] = s0; sc[1][k] = s1; sc[2][k] = s2;
        pm0 = fmaxf(pm0, s0); pm1 = fmaxf(pm1, s1); pm2 = fmaxf(pm2, s2);
    }
    // single-pass 3-wide max reduction
    red3[tid][0] = pm0; red3[tid][1] = pm1; red3[tid][2] = pm2;
    __syncthreads();
    for (int o = 64; o > 0; o >>= 1) {
        if (tid < o) {
            red3[tid][0] = fmaxf(red3[tid][0], red3[tid + o][0]);
            red3[tid][1] = fmaxf(red3[tid][1], red3[tid + o][1]);
            red3[tid][2] = fmaxf(red3[tid][2], red3[tid + o][2]);
        }
        __syncthreads();
    }
    if (tid == 0) { mm[0] = red3[0][0]; mm[1] = red3[0][1]; mm[2] = red3[0][2]; }
    __syncthreads();

    float ps0 = 0.f, ps1 = 0.f, ps2 = 0.f;
    float m0 = mm[0], m1 = mm[1], m2 = mm[2];
    for (int k = tid; k < kmax; k += 128) {
        float e0 = __expf(sc[0][k] - m0); sc[0][k] = e0; ps0 += e0;
        float e1 = __expf(sc[1][k] - m1); sc[1][k] = e1; ps1 += e1;
        float e2 = __expf(sc[2][k] - m2); sc[2][k] = e2; ps2 += e2;
    }
    // single-pass 3-wide sum reduction
    red3[tid][0] = ps0; red3[tid][1] = ps1; red3[tid][2] = ps2;
    __syncthreads();
    for (int o = 64; o > 0; o >>= 1) {
        if (tid < o) {
            red3[tid][0] += red3[tid + o][0];
            red3[tid][1] += red3[tid + o][1];
            red3[tid][2] += red3[tid + o][2];
        }
        __syncthreads();
    }
    if (tid == 0) {
        invs[0] = 1.f / red3[0][0];
        invs[1] = 1.f / red3[0][1];
        invs[2] = 1.f / red3[0][2];
    }
    __syncthreads();

    {
        int quar = tid >> 5, h2 = tid & 31;
        int Lq = kmax >> 2;
        int kb = quar * Lq;
        int kend = (quar == 3) ? kmax : (kb + Lq);
        float a0x = 0.f, a0y = 0.f, a1x = 0.f, a1y = 0.f, a2x = 0.f, a2y = 0.f;
        const __half2* vp = (const __half2*)(Vp + kvh * 64) + h2;
        for (int k = kb; k < kend; k++) {
            float2 f = __half22float2(vp[(size_t)k * (KW / 2)]);
            float s0 = sc[0][k], s1 = sc[1][k], s2 = sc[2][k];
            a0x += s0 * f.x; a0y += s0 * f.y;
            a1x += s1 * f.x; a1y += s1 * f.y;
            a2x += s2 * f.x; a2y += s2 * f.y;
        }
        pv[tid][0] = a0x; pv[tid][1] = a0y;
        pv[tid][2] = a1x; pv[tid][3] = a1y;
        pv[tid][4] = a2x; pv[tid][5] = a2y;
    }
    __syncthreads();
    if (tid < 32) {
        #pragma unroll
        for (int j = 0; j < 3; j++) {
            float rx = 0.f, ry = 0.f;
            #pragma unroll
            for (int qq = 0; qq < 4; qq++) {
                rx += pv[qq * 32 + tid][j * 2];
                ry += pv[qq * 32 + tid][j * 2 + 1];
            }
            __half2* op = (__half2*)(Op + (size_t)q * QW + (kvh * 3 + j) * 64);
            op[tid] = __floats2half2_rn(rx * invs[j], ry * invs[j]);
        }
    }
}

// ---------------- merged silu ----------------
__global__ void silu2_kernel(const float* __restrict__ g1, const float* __restrict__ u1,
                             __half* __restrict__ o1, int n1,
                             const float* __restrict__ g2, const float* __restrict__ u2,
                             __half* __restrict__ o2, int n2) {
    int i = blockIdx.x * 256 + threadIdx.x;
    if (i < n1) {
        float x = g1[i];
        o1[i] = __float2half((x / (1.f + __expf(-x))) * u1[i]);
    } else if (i - n1 < n2) {
        int j = i - n1;
        float x = g2[j];
        o2[j] = __float2half((x / (1.f + __expf(-x))) * u2[j]);
    }
}

// ---------------- host-side grouped-gemm builder ----------------
static inline void batch_init(GemmBatch& b, int& blk) { b.nt = 0; blk = 0; }
static inline void batch_add(GemmBatch& b, int& blk,
                             const __half* A, const __half* B, void* C,
                             int M, int N, int K, int acc, int ohalf,
                             int split = 1, int tm64 = 0) {
    GemmTask& T = b.t[b.nt++];
    T.A = A; T.B = B; T.C = C; T.N = N; T.K = K; T.acc = acc; T.ohalf = ohalf;
    T.tm64 = tm64;
    T.nbn = (N + 63) / 64;
    T.nbm = M / (tm64 ? 64 : 128);
    T.split = split;
    T.blk_start = blk;
    blk += T.nbn * T.nbm * split;
}
static inline void batch_go(GemmBatch& b, int blk) {
    gemm_h_kernel<<<blk, 128, SM_TOT>>>(b);
}

extern "C" void kernel_launch(void* const* d_in, const int* in_sizes, int n_in,
                              void* d_out, int out_size) {
    const float* in_vlm = (const float*)d_in[0];
    const float* in_exp = (const float*)d_in[1];
    const float* f_vq   = (const float*)d_in[2];
    const float* f_vk   = (const float*)d_in[3];
    const float* f_vv   = (const float*)d_in[4];
    const float* f_vo   = (const float*)d_in[5];
    const float* w_vln1 = (const float*)d_in[6];
    const float* w_vln2 = (const float*)d_in[7];
    const float* f_vg   = (const float*)d_in[8];
    const float* f_vu   = (const float*)d_in[9];
    const float* f_vd   = (const float*)d_in[10];
    const float* w_vfn  = (const float*)d_in[11];
    const float* f_eq   = (const float*)d_in[12];
    const float* f_eks  = (const float*)d_in[13];
    const float* f_evs  = (const float*)d_in[14];
    const float* f_ekc  = (const float*)d_in[15];
    const float* f_evc  = (const float*)d_in[16];
    const float* f_eo   = (const float*)d_in[17];
    const float* w_eln1 = (const float*)d_in[18];
    const float* w_eln2 = (const float*)d_in[19];
    const float* f_eg   = (const float*)d_in[20];
    const float* f_eu   = (const float*)d_in[21];
    const float* f_ed   = (const float*)d_in[22];
    const float* w_efn  = (const float*)d_in[23];
    const int*   pos_ids = (const int*)d_in[24];
    float* out = (float*)d_out;

    cudaFuncSetAttribute(gemm_h_kernel,
                         cudaFuncAttributeMaxDynamicSharedMemorySize, SM_TOT);

    __half* wh;
    cudaGetSymbolAddress((void**)&wh, g_wh);
    float *vlm, *exps, *m1, *m2, *e1, *e2;
    __half *hv, *he, *q, *k, *v, *ke, *ve, *att, *m2h, *e2h;
    cudaGetSymbolAddress((void**)&vlm, g_vlm);
    cudaGetSymbolAddress((void**)&exps, g_exp);
    cudaGetSymbolAddress((void**)&m1, g_m1);
    cudaGetSymbolAddress((void**)&m2, g_m2);
    cudaGetSymbolAddress((void**)&e1, g_e1);
    cudaGetSymbolAddress((void**)&e2, g_e2);
    cudaGetSymbolAddress((void**)&hv, h_hv);
    cudaGetSymbolAddress((void**)&he, h_he);
    cudaGetSymbolAddress((void**)&q,  h_q);
    cudaGetSymbolAddress((void**)&k,  h_k);
    cudaGetSymbolAddress((void**)&v,  h_v);
    cudaGetSymbolAddress((void**)&ke, h_ke);
    cudaGetSymbolAddress((void**)&ve, h_ve);
    cudaGetSymbolAddress((void**)&att, h_att);
    cudaGetSymbolAddress((void**)&m2h, h_m2);
    cudaGetSymbolAddress((void**)&e2h, h_e2);

    // ---- convert all weights to half in ONE launch ----
    {
        CvtBatch cb;
        const float* srcs[16] = {f_vq, f_vk, f_vv, f_vo, f_vg, f_vu, f_vd, f_eq,
                                 f_eks, f_evs, f_ekc, f_evc, f_eo, f_eg, f_eu, f_ed};
        size_t offs[16] = {O_VQ, O_VK, O_VV, O_VO, O_VG, O_VU, O_VD, O_EQ,
                           O_EKS, O_EVS, O_EKC, O_EVC, O_EO, O_EG, O_EU, O_ED};
        size_t ns[16] = {N_VQ, N_VK, N_VV, N_VO, N_VG, N_VU, N_VD, N_EQ,
                         N_EKS, N_EVS, N_EKC, N_EVC, N_EO, N_EG, N_EU, N_ED};
        for (int i = 0; i < 16; i++) {
            cb.s[i] = (const float4*)srcs[i];
            cb.d[i] = (uint2*)(wh + offs[i]);
            cb.n4[i] = ns[i] / 4;
        }
        cvt_all_kernel<<<dim3(160, 16), 256>>>(cb);
    }

    cudaMemcpyAsync(vlm,  in_vlm, (size_t)PL * TH * sizeof(float), cudaMemcpyDeviceToDevice);
    cudaMemcpyAsync(exps, in_exp, (size_t)EL * EH * sizeof(float), cudaMemcpyDeviceToDevice);

    GemmBatch b; int blk;
    const int ropeBlocks = (SS * RP_HEADS + 3) / 4;

    for (int li = 0; li < L_LAYERS; li++) {
        const __half* vq  = wh + O_VQ  + (size_t)li * TH * QW;
        const __half* vk  = wh + O_VK  + (size_t)li * TH * KW;
        const __half* vv  = wh + O_VV  + (size_t)li * TH * KW;
        const __half* vo  = wh + O_VO  + (size_t)li * QW * TH;
        const __half* vg  = wh + O_VG  + (size_t)li * TH * TI;
        const __half* vu  = wh + O_VU  + (size_t)li * TH * TI;
        const __half* vd  = wh + O_VD  + (size_t)li * TI * TH;
        const __half* eq  = wh + O_EQ  + (size_t)li * EH * QW;
        const __half* eo  = wh + O_EO  + (size_t)li * QW * EH;
        const __half* eg  = wh + O_EG  + (size_t)li * EH * EI;
        const __half* eu  = wh + O_EU  + (size_t)li * EH * EI;
        const __half* ed  = wh + O_ED  + (size_t)li * EI * EH;

        rms2_kernel<true><<<PL + EL, 256>>>(vlm, w_vln1 + (size_t)li * TH, hv, TH, PL,
                                            exps, w_eln1 + (size_t)li * EH, he, EH);

        if (li % 2 == 0) {
            const __half* eks = wh + O_EKS + (size_t)(li / 2) * EH * KW;
            const __half* evs = wh + O_EVS + (size_t)(li / 2) * EH * KW;
            batch_init(b, blk);
            batch_add(b, blk, hv, vq,  q,                    PL, QW, TH, 0, 1, 1, 1);
            batch_add(b, blk, hv, vk,  k,                    PL, KW, TH, 0, 1, 1, 1);
            batch_add(b, blk, hv, vv,  v,                    PL, KW, TH, 0, 1, 1, 1);
            batch_add(b, blk, he, eq,  q + (size_t)PL * QW,  EL, QW, EH, 0, 1, 1, 1);
            batch_add(b, blk, he, eks, k + (size_t)PL * KW,  EL, KW, EH, 0, 1, 1, 1);
            batch_add(b, blk, he, evs, v + (size_t)PL * KW,  EL, KW, EH, 0, 1, 1, 1);
            batch_go(b, blk);
            rope2_kernel<<<ropeBlocks, 128>>>(q, k, pos_ids, SS);
            attn_kernel<<<dim3(SS, NKV), 128>>>(q, k, v, att, SS, 1,
                                                nullptr, nullptr, nullptr, nullptr);
        } else {
            const __half* ekc = wh + O_EKC + (size_t)(li / 2) * KW * KW;
            const __half* evc = wh + O_EVC + (size_t)(li / 2) * KW * KW;
            batch_init(b, blk);
            batch_add(b, blk, hv, vq, q,                   PL, QW, TH, 0, 1, 1, 1);
            batch_add(b, blk, hv, vk, k,                   PL, KW, TH, 0, 1, 1, 1);
            batch_add(b, blk, hv, vv, v,                   PL, KW, TH, 0, 1, 1, 1);
            batch_add(b, blk, he, eq, q + (size_t)PL * QW, EL, QW, EH, 0, 1, 1, 1);
            batch_go(b, blk);
            rope2_kernel<<<ropeBlocks, 128>>>(q, k, pos_ids, PL);
            batch_init(b, blk);
            batch_add(b, blk, k, ekc, ke, PL, KW, KW, 0, 1, 1, 1);
            batch_add(b, blk, v, evc, ve, PL, KW, KW, 0, 1, 1, 1);
            batch_go(b, blk);
            // merged self + cross attention in one launch
            attn_kernel<<<dim3(PL, 2 * NKV), 128>>>(q, k, v, att, PL, 2,
                                                    q + (size_t)PL * QW, ke, ve,
                                                    att + (size_t)PL * QW);
        }

        // ---- wo: M64 + split-K (R12 tuning: vlm 3, exp 4) ----
        batch_init(b, blk);
        batch_add(b, blk, att,                    vo, vlm,  PL, TH, QW, 1, 0, 3, 1);
        batch_add(b, blk, att + (size_t)PL * QW,  eo, exps, EL, EH, QW, 1, 0, 4, 1);
        batch_go(b, blk);

        rms2_kernel<true><<<PL + EL, 256>>>(vlm, w_vln2 + (size_t)li * TH, hv, TH, PL,
                                            exps, w_eln2 + (size_t)li * EH, he, EH);

        // ---- gate + up: vlm M128 single wave, exp M64 ----
        batch_init(b, blk);
        batch_add(b, blk, hv, vg, m1, PL, TI, TH, 0, 0, 1, 0);
        batch_add(b, blk, hv, vu, m2, PL, TI, TH, 0, 0, 1, 0);
        batch_add(b, blk, he, eg, e1, EL, EI, EH, 0, 0, 1, 1);
        batch_add(b, blk, he, eu, e2, EL, EI, EH, 0, 0, 1, 1);
        batch_go(b, blk);

        silu2_kernel<<<(PL * TI + EL * EI + 255) / 256, 256>>>(
            m1, m2, m2h, PL * TI, e1, e2, e2h, EL * EI);

        // ---- down: M64 + split-K (R12 tuning: vlm 3, exp 4) ----
        batch_init(b, blk);
        batch_add(b, blk, m2h, vd, vlm,  PL, TH, TI, 1, 0, 3, 1);
        batch_add(b, blk, e2h, ed, exps, EL, EH, EI, 1, 0, 4, 1);
        batch_go(b, blk);
    }

    // final norms -> fp32 output (merged)
    rms2_kernel<false><<<PL + EL, 256>>>(vlm, w_vfn, out, TH, PL,
                                         exps, w_efn, out + (size_t)PL * TH, EH);
}